// round 13
// baseline (speedup 1.0000x reference)
#include <cuda_runtime.h>
#include <cuda_fp16.h>
#include <cuda_fp8.h>

#define H      32
#define NN     64
#define MHD_   5
#define NEDGE  1025   // NUM_EDGE_EMB
#define NSP    512    // NUM_SPATIAL_EMB
#define ROWLEN 65     // N + 1
#define TPAD   34     // half-elements stride of the transpose tile

// Precombined table M[d][i][k] = sum_h W_edge[i][h] * Wd[d][h][k], stored as
// fp8 e4m3 SCALED BY 256. Row = 32 B. Table = 164 KB. Row i==0 is zero so
// gathers are unconditional.
__device__ __align__(16) unsigned char d_M8[MHD_ * NEDGE * H];
// fp16 copy of W_spatial (512 x 32 = 32 KB).
__device__ __align__(16) __half d_Wsp[NSP * H];

// ---------------------------------------------------------------------------
// Prologue: fold W_edge (1025x32) with Wd (5x32x32) into fp8 M (x256);
// convert W_spatial to fp16.
// ---------------------------------------------------------------------------
__global__ __launch_bounds__(160) void precompute_M(
    const float* __restrict__ W_edge,
    const float* __restrict__ W_dist,
    const float* __restrict__ W_spatial)
{
    int i    = blockIdx.x;
    int d    = threadIdx.x >> 5;
    int lane = threadIdx.x & 31;

    float we = W_edge[i * H + lane];
    float acc = 0.f;
    #pragma unroll
    for (int h = 0; h < H; ++h) {
        float w = __shfl_sync(0xffffffffu, we, h);
        acc = fmaf(w, __ldg(&W_dist[(d * H + h) * H + lane]), acc);
    }
    __nv_fp8_storage_t s =
        __nv_cvt_float_to_fp8(acc * 256.f, __NV_SATFINITE, __NV_E4M3);
    d_M8[(d * NEDGE + i) * H + lane] = (i == 0) ? (__nv_fp8_storage_t)0 : s;

    if (i < NSP && d == 0)
        d_Wsp[i * H + lane] = __float2half(W_spatial[i * H + lane]);
}

// fp8x2 (e4m3) -> half2 hardware convert.
__device__ __forceinline__ __half2 cvt_e4m3x2(unsigned short s) {
    unsigned r;
    asm("cvt.rn.f16x2.e4m3x2 %0, %1;" : "=r"(r) : "h"(s));
    return *(__half2*)&r;
}
__device__ __forceinline__ void cvt8(const uint2 v, __half2 o[4]) {
    o[0] = cvt_e4m3x2((unsigned short)(v.x));
    o[1] = cvt_e4m3x2((unsigned short)(v.x >> 16));
    o[2] = cvt_e4m3x2((unsigned short)(v.y));
    o[3] = cvt_e4m3x2((unsigned short)(v.y >> 16));
}

// ---------------------------------------------------------------------------
// Main kernel: grid = B*(N+1), 256 threads, 6 blocks/SM.
// 4 lanes per m: lane>>2 = m within warp's 8, lane&3 = head-quad (8 heads/8B).
// Epilogue uses float2 (8B) accesses; parity-dependent window keeps them
// aligned (row base parity alternates with h+r).
// ---------------------------------------------------------------------------
__global__ __launch_bounds__(256, 6) void graph_attn_bias_kernel(
    const float* __restrict__ attn_bias,
    const int*   __restrict__ spatial_pos,
    const int*   __restrict__ edge_input,
    const float* __restrict__ w_token,
    float*       __restrict__ out)
{
    const int bidx = blockIdx.x;
    const int b    = bidx / ROWLEN;
    const int r    = bidx - b * ROWLEN;
    const int tid  = threadIdx.x;
    const int warp = tid >> 5;
    const int lane = tid & 31;

    if (r == 0) {
        // Top border row: out[b,h,0,j] = attn_bias + w_token[h].
        const float* ab = attn_bias + (size_t)b * H * (ROWLEN * ROWLEN);
        float*       o  = out       + (size_t)b * H * (ROWLEN * ROWLEN);
        #pragma unroll
        for (int k = 0; k < 4; ++k) {
            int h = warp * 4 + k;
            float gt = __ldg(&w_token[h]);
            size_t base = (size_t)h * (ROWLEN * ROWLEN);
            const int o2 = (int)(base & 1);   // alignment offset for float2
            const float* abp = ab + base;
            float*       op  = o  + base;
            float2 av = *(const float2*)(abp + o2 + 2 * lane);
            *(float2*)(op + o2 + 2 * lane) = make_float2(av.x + gt, av.y + gt);
            if (lane == 0) {
                int js = o2 ? 0 : 64;
                op[js] = abp[js] + gt;
            }
        }
        return;
    }
    const int n = r - 1;

    __shared__ __align__(16) unsigned short s_eidx[NN * 15]; // 1.875 KB
    __shared__ __align__(4)  __half s_tile[NN * TPAD];       // 4.25 KB

    // Stage edge indices (960 ints -> u16, values < 1025).
    if (tid < NN * 15 / 4) {
        const int4* e4 = (const int4*)(edge_input + (size_t)(b * NN + n) * NN * 15);
        int4 v = e4[tid];
        ((ushort4*)s_eidx)[tid] =
            make_ushort4((unsigned short)v.x, (unsigned short)v.y,
                         (unsigned short)v.z, (unsigned short)v.w);
    }
    __syncthreads();

    const int q = lane & 3;            // head-quad: heads 8q..8q+7
    const int m = warp * 8 + (lane >> 2);
    // Warp-broadcast spatial read (4 lanes per m share an address).
    const int sp = __ldg(&spatial_pos[(size_t)(b * NN + n) * NN + m]);

    // Spatial bias for this (m, head-quad): one 16B fp16 load.
    const uint4 spv = __ldg((const uint4*)(d_Wsp + sp * H + 8 * q));

    const uint2* M2g = (const uint2*)d_M8;   // 4 uint2 (8B) per 32B table row
    __half2 acc0, acc1, acc2, acc3;
    {
        const unsigned zz = 0u;
        acc0 = acc1 = acc2 = acc3 = *(const __half2*)&zz;
    }

    // Software-pipelined idx triples; fully unrolled d loop.
    const unsigned short* eb = s_eidx + m * 15;
    unsigned j0 = eb[0], j1 = eb[1], j2 = eb[2];
    #pragma unroll
    for (int d = 0; d < MHD_; ++d) {
        const unsigned i0 = j0, i1 = j1, i2 = j2;
        uint2 v0 = __ldg(&M2g[(d * NEDGE + i0) * 4 + q]);
        uint2 v1 = __ldg(&M2g[(d * NEDGE + i1) * 4 + q]);
        uint2 v2 = __ldg(&M2g[(d * NEDGE + i2) * 4 + q]);
        if (d < MHD_ - 1) {
            j0 = eb[d * 3 + 3]; j1 = eb[d * 3 + 4]; j2 = eb[d * 3 + 5];
        }

        const int c = (i0 != 0) + (i1 != 0) + (i2 != 0);
        // reciprocal-of-count folded with 1/256 table scale:
        // c=1 -> 1/256, c=2 -> 1/512, c=3 -> 1/768
        const unsigned rcbits = (c == 3) ? 0x15551555u
                              : (c == 2) ? 0x18001800u
                              : (c == 1) ? 0x1C001C00u : 0u;
        const __half2 rc2 = *(const __half2*)&rcbits;

        __half2 h0[4], h1[4], h2[4];
        cvt8(v0, h0); cvt8(v1, h1); cvt8(v2, h2);
        acc0 = __hfma2(__hadd2(__hadd2(h0[0], h1[0]), h2[0]), rc2, acc0);
        acc1 = __hfma2(__hadd2(__hadd2(h0[1], h1[1]), h2[1]), rc2, acc1);
        acc2 = __hfma2(__hadd2(__hadd2(h0[2], h1[2]), h2[2]), rc2, acc2);
        acc3 = __hfma2(__hadd2(__hadd2(h0[3], h1[3]), h2[3]), rc2, acc3);
    }

    int spc = sp - 1;
    spc = spc < 1 ? 1 : (spc > MHD_ ? MHD_ : spc);
    const unsigned rsbits = (spc == 1) ? 0x3C003C00u
                          : (spc == 2) ? 0x38003800u
                          : (spc == 3) ? 0x35553555u
                          : (spc == 4) ? 0x34003400u : 0x32663266u;  // 1..1/5
    const __half2 rs2 = *(const __half2*)&rsbits;

    // tile = spb + rs * acc, kept in half (exact: already an fp16 result).
    const __half2* sph = (const __half2*)&spv;
    __half2* t2 = (__half2*)(s_tile) + m * (TPAD / 2) + 4 * q;
    t2[0] = __hfma2(acc0, rs2, sph[0]);
    t2[1] = __hfma2(acc1, rs2, sph[1]);
    t2[2] = __hfma2(acc2, rs2, sph[2]);
    t2[3] = __hfma2(acc3, rs2, sph[3]);
    __syncthreads();

    // Write row (n+1): warp -> 4 heads, lane -> 2 columns (float2).
    // Window [o2, o2+64) is 8B-aligned; leftover cell handled by lane 0.
    const size_t rowbase0 = ((size_t)b * H * ROWLEN + (n + 1)) * ROWLEN;
    #pragma unroll
    for (int k = 0; k < 4; ++k) {
        const int h = warp * 4 + k;
        const size_t base = rowbase0 + (size_t)h * (ROWLEN * ROWLEN);
        const int o2 = (int)(base & 1);
        const float* abp = attn_bias + base;
        float*       op  = out + base;
        const float wt = __ldg(&w_token[h]);

        float2 av = *(const float2*)(abp + o2 + 2 * lane);
        float vx, vy;
        if (o2 == 0) {
            // j = 2*lane, 2*lane+1 ; j==0 -> w_token, else tile[j-1]
            vx = (lane == 0) ? wt
                 : __half2float(s_tile[(2 * lane - 1) * TPAD + h]);
            vy = __half2float(s_tile[(2 * lane) * TPAD + h]);
        } else {
            // j = 1+2*lane, 2+2*lane -> tile[2*lane], tile[2*lane+1]
            vx = __half2float(s_tile[(2 * lane) * TPAD + h]);
            vy = __half2float(s_tile[(2 * lane + 1) * TPAD + h]);
        }
        *(float2*)(op + o2 + 2 * lane) = make_float2(av.x + vx, av.y + vy);

        if (lane == 0) {
            if (o2) op[0]  = abp[0]  + wt;                                   // j=0
            else    op[64] = abp[64] + __half2float(s_tile[63 * TPAD + h]);  // j=64
        }
    }
}

// ---------------------------------------------------------------------------
// Inputs (metadata order):
//  0 attn_bias  f32 (64,32,65,65)   1 spatial_pos i32 (64,64,64)
//  2 edge_input i32 (64,64,64,5,3)  3 attn_edge_type (unused)
//  4 W_edge f32 (1025,32)  5 W_dist f32 (131072,1)
//  6 W_spatial f32 (512,32)  7 w_token f32 (1,32)
// ---------------------------------------------------------------------------
extern "C" void kernel_launch(void* const* d_in, const int* in_sizes, int n_in,
                              void* d_out, int out_size)
{
    const float* attn_bias   = (const float*)d_in[0];
    const int*   spatial_pos = (const int*)  d_in[1];
    const int*   edge_input  = (const int*)  d_in[2];
    const float* W_edge      = (const float*)d_in[4];
    const float* W_dist      = (const float*)d_in[5];
    const float* W_spatial   = (const float*)d_in[6];
    const float* w_token     = (const float*)d_in[7];
    float*       out         = (float*)d_out;

    precompute_M<<<NEDGE, 160>>>(W_edge, W_dist, W_spatial);
    graph_attn_bias_kernel<<<64 * ROWLEN, 256>>>(
        attn_bias, spatial_pos, edge_input, w_token, out);
}

// round 14
// speedup vs baseline: 1.0579x; 1.0579x over previous
#include <cuda_runtime.h>
#include <cuda_fp16.h>
#include <cuda_fp8.h>

#define H      32
#define NN     64
#define MHD_   5
#define NEDGE  1025   // NUM_EDGE_EMB
#define NSP    512    // NUM_SPATIAL_EMB
#define ROWLEN 65     // N + 1
#define TPAD   34     // half-elements stride of the transpose tile

// Precombined table M[d][i][k] = sum_h W_edge[i][h] * Wd[d][h][k], stored as
// fp8 e4m3 SCALED BY 256. Row = 32 B. Table = 164 KB. Row i==0 is zero so
// gathers are unconditional.
__device__ __align__(16) unsigned char d_M8[MHD_ * NEDGE * H];
// fp16 copy of W_spatial (512 x 32 = 32 KB).
__device__ __align__(16) __half d_Wsp[NSP * H];

// ---------------------------------------------------------------------------
// Prologue: fold W_edge (1025x32) with Wd (5x32x32) into fp8 M (x256);
// convert W_spatial to fp16.
// ---------------------------------------------------------------------------
__global__ __launch_bounds__(160) void precompute_M(
    const float* __restrict__ W_edge,
    const float* __restrict__ W_dist,
    const float* __restrict__ W_spatial)
{
    int i    = blockIdx.x;
    int d    = threadIdx.x >> 5;
    int lane = threadIdx.x & 31;

    float we = W_edge[i * H + lane];
    float acc = 0.f;
    #pragma unroll
    for (int h = 0; h < H; ++h) {
        float w = __shfl_sync(0xffffffffu, we, h);
        acc = fmaf(w, __ldg(&W_dist[(d * H + h) * H + lane]), acc);
    }
    __nv_fp8_storage_t s =
        __nv_cvt_float_to_fp8(acc * 256.f, __NV_SATFINITE, __NV_E4M3);
    d_M8[(d * NEDGE + i) * H + lane] = (i == 0) ? (__nv_fp8_storage_t)0 : s;

    if (i < NSP && d == 0)
        d_Wsp[i * H + lane] = __float2half(W_spatial[i * H + lane]);
}

// fp8x2 (e4m3) -> half2 hardware convert.
__device__ __forceinline__ __half2 cvt_e4m3x2(unsigned short s) {
    unsigned r;
    asm("cvt.rn.f16x2.e4m3x2 %0, %1;" : "=r"(r) : "h"(s));
    return *(__half2*)&r;
}
__device__ __forceinline__ void cvt8(const uint2 v, __half2 o[4]) {
    o[0] = cvt_e4m3x2((unsigned short)(v.x));
    o[1] = cvt_e4m3x2((unsigned short)(v.x >> 16));
    o[2] = cvt_e4m3x2((unsigned short)(v.y));
    o[3] = cvt_e4m3x2((unsigned short)(v.y >> 16));
}

// ---------------------------------------------------------------------------
// Main kernel: grid = B*(N+1), 256 threads, 8 blocks/SM (32-reg budget ->
// 64 warps of latency hiding). Spatial loads deferred to after the gather
// loop to keep its live register set small.
// 4 lanes per m: lane>>2 = m within warp's 8, lane&3 = head-quad (8 heads/8B).
// ---------------------------------------------------------------------------
__global__ __launch_bounds__(256, 8) void graph_attn_bias_kernel(
    const float* __restrict__ attn_bias,
    const int*   __restrict__ spatial_pos,
    const int*   __restrict__ edge_input,
    const float* __restrict__ w_token,
    float*       __restrict__ out)
{
    const int bidx = blockIdx.x;
    const int b    = bidx / ROWLEN;
    const int r    = bidx - b * ROWLEN;
    const int tid  = threadIdx.x;
    const int warp = tid >> 5;
    const int lane = tid & 31;

    if (r == 0) {
        // Top border row: out[b,h,0,j] = attn_bias + w_token[h].
        const float* ab = attn_bias + (size_t)b * H * (ROWLEN * ROWLEN);
        float*       o  = out       + (size_t)b * H * (ROWLEN * ROWLEN);
        #pragma unroll
        for (int k = 0; k < 4; ++k) {
            int h = warp * 4 + k;
            float gt = __ldg(&w_token[h]);
            size_t base = (size_t)h * (ROWLEN * ROWLEN);
            o[base + lane]      = ab[base + lane]      + gt;
            o[base + 32 + lane] = ab[base + 32 + lane] + gt;
            if (lane == 0) o[base + 64] = ab[base + 64] + gt;
        }
        return;
    }
    const int n = r - 1;

    __shared__ __align__(16) unsigned short s_eidx[NN * 15]; // 1.875 KB
    __shared__ __align__(4)  __half s_tile[NN * TPAD];       // 4.25 KB

    // Stage edge indices (960 ints -> u16, values < 1025).
    if (tid < NN * 15 / 4) {
        const int4* e4 = (const int4*)(edge_input + (size_t)(b * NN + n) * NN * 15);
        int4 v = e4[tid];
        ((ushort4*)s_eidx)[tid] =
            make_ushort4((unsigned short)v.x, (unsigned short)v.y,
                         (unsigned short)v.z, (unsigned short)v.w);
    }
    __syncthreads();

    const int q = lane & 3;            // head-quad: heads 8q..8q+7
    const int m = warp * 8 + (lane >> 2);

    const uint2* M2g = (const uint2*)d_M8;   // 4 uint2 (8B) per 32B table row
    __half2 acc0, acc1, acc2, acc3;
    {
        const unsigned zz = 0u;
        acc0 = acc1 = acc2 = acc3 = *(const __half2*)&zz;
    }

    // Software-pipelined idx triples; fully unrolled d loop.
    const unsigned short* eb = s_eidx + m * 15;
    unsigned j0 = eb[0], j1 = eb[1], j2 = eb[2];
    #pragma unroll
    for (int d = 0; d < MHD_; ++d) {
        const unsigned i0 = j0, i1 = j1, i2 = j2;
        uint2 v0 = __ldg(&M2g[(d * NEDGE + i0) * 4 + q]);
        uint2 v1 = __ldg(&M2g[(d * NEDGE + i1) * 4 + q]);
        uint2 v2 = __ldg(&M2g[(d * NEDGE + i2) * 4 + q]);
        if (d < MHD_ - 1) {
            j0 = eb[d * 3 + 3]; j1 = eb[d * 3 + 4]; j2 = eb[d * 3 + 5];
        }

        const int c = (i0 != 0) + (i1 != 0) + (i2 != 0);
        // reciprocal-of-count folded with 1/256 table scale:
        // c=1 -> 1/256, c=2 -> 1/512, c=3 -> 1/768
        const unsigned rcbits = (c == 3) ? 0x15551555u
                              : (c == 2) ? 0x18001800u
                              : (c == 1) ? 0x1C001C00u : 0u;
        const __half2 rc2 = *(const __half2*)&rcbits;

        __half2 h0[4], h1[4], h2[4];
        cvt8(v0, h0); cvt8(v1, h1); cvt8(v2, h2);
        acc0 = __hfma2(__hadd2(__hadd2(h0[0], h1[0]), h2[0]), rc2, acc0);
        acc1 = __hfma2(__hadd2(__hadd2(h0[1], h1[1]), h2[1]), rc2, acc1);
        acc2 = __hfma2(__hadd2(__hadd2(h0[2], h1[2]), h2[2]), rc2, acc2);
        acc3 = __hfma2(__hadd2(__hadd2(h0[3], h1[3]), h2[3]), rc2, acc3);
    }

    // Spatial term — loaded AFTER the gather loop (keeps loop regs small).
    const int sp = __ldg(&spatial_pos[(size_t)(b * NN + n) * NN + m]);
    const uint4 spv = __ldg((const uint4*)(d_Wsp + sp * H + 8 * q));

    int spc = sp - 1;
    spc = spc < 1 ? 1 : (spc > MHD_ ? MHD_ : spc);
    const unsigned rsbits = (spc == 1) ? 0x3C003C00u
                          : (spc == 2) ? 0x38003800u
                          : (spc == 3) ? 0x35553555u
                          : (spc == 4) ? 0x34003400u : 0x32663266u;  // 1..1/5
    const __half2 rs2 = *(const __half2*)&rsbits;

    // tile = spb + rs * acc, kept in half (exact: already an fp16 result).
    const __half2* sph = (const __half2*)&spv;
    __half2* t2 = (__half2*)(s_tile) + m * (TPAD / 2) + 4 * q;
    t2[0] = __hfma2(acc0, rs2, sph[0]);
    t2[1] = __hfma2(acc1, rs2, sph[1]);
    t2[2] = __hfma2(acc2, rs2, sph[2]);
    t2[3] = __hfma2(acc3, rs2, sph[3]);
    __syncthreads();

    // Write row (n+1): warp -> 4 heads, lane -> column; j==0 takes w_token.
    const float* ab = attn_bias + ((size_t)b * H * ROWLEN + (n + 1)) * ROWLEN;
    float*       o  = out       + ((size_t)b * H * ROWLEN + (n + 1)) * ROWLEN;
    #pragma unroll
    for (int k = 0; k < 4; ++k) {
        int h = warp * 4 + k;
        size_t base = (size_t)h * (ROWLEN * ROWLEN);
        float v0 = (lane == 0) ? __ldg(&w_token[h])
                               : __half2float(s_tile[(lane - 1) * TPAD + h]);
        o[base + lane] = ab[base + lane] + v0;
        o[base + 32 + lane] = ab[base + 32 + lane]
                              + __half2float(s_tile[(lane + 31) * TPAD + h]);
        if (lane == 0)
            o[base + 64] = ab[base + 64] + __half2float(s_tile[63 * TPAD + h]);
    }
}

// ---------------------------------------------------------------------------
// Inputs (metadata order):
//  0 attn_bias  f32 (64,32,65,65)   1 spatial_pos i32 (64,64,64)
//  2 edge_input i32 (64,64,64,5,3)  3 attn_edge_type (unused)
//  4 W_edge f32 (1025,32)  5 W_dist f32 (131072,1)
//  6 W_spatial f32 (512,32)  7 w_token f32 (1,32)
// ---------------------------------------------------------------------------
extern "C" void kernel_launch(void* const* d_in, const int* in_sizes, int n_in,
                              void* d_out, int out_size)
{
    const float* attn_bias   = (const float*)d_in[0];
    const int*   spatial_pos = (const int*)  d_in[1];
    const int*   edge_input  = (const int*)  d_in[2];
    const float* W_edge      = (const float*)d_in[4];
    const float* W_dist      = (const float*)d_in[5];
    const float* W_spatial   = (const float*)d_in[6];
    const float* w_token     = (const float*)d_in[7];
    float*       out         = (float*)d_out;

    precompute_M<<<NEDGE, 160>>>(W_edge, W_dist, W_spatial);
    graph_attn_bias_kernel<<<64 * ROWLEN, 256>>>(
        attn_bias, spatial_pos, edge_input, w_token, out);
}